// round 11
// baseline (speedup 1.0000x reference)
#include <cuda_runtime.h>
#include <cuda_bf16.h>
#include <stdint.h>

// SlidingWindowMatrixMult3D via mma.sync bf16, 3-pass fp32 emulation.
// Z[b,w,t] = sum_c Q[b,w,c]*K[b,w+t,c] + sum_c Q[b,w,c]*bias[c,t]
// B=16, T=1024, C=128.
//
// R11 (= R10 resubmit after infra failure): conv pre-pass + band kernel +
// bias GEMM kernel; MMAs non-volatile (schedulable) and issued pass-major
// across n-tiles so consecutive MMAs hit different accumulators (breaks the
// accumulator RAW chains that capped the HMMA pipe at ~45%).

#define Bz 16
#define Tz 1024
#define Cz 128
#define KTOT 2047
#define KPADROWS 128

// ---- global bf16 scratch ----
__device__ __nv_bfloat16 g_Qh[Bz * Tz * Cz];
__device__ __nv_bfloat16 g_Ql[Bz * Tz * Cz];
__device__ __nv_bfloat16 g_Kh[(Bz * KTOT + KPADROWS) * Cz];
__device__ __nv_bfloat16 g_Kl[(Bz * KTOT + KPADROWS) * Cz];
__device__ __nv_bfloat16 g_Bh[Tz * Cz];     // transposed: [t][c]
__device__ __nv_bfloat16 g_Bl[Tz * Cz];

// ---- shared layouts (both kernels 102 KB -> 2 CTA/SM) ----
#define RST 272u
#define OFF_QH 0u
#define OFF_QL 17408u
#define OFF_KH 34816u            // 128-slot ring (hi)
#define OFF_KL 69632u            // 128-slot ring (lo)
#define DHL    34816u            // hi -> lo delta
#define SMEM_BAND 104448u
#define BO_QH 0u
#define BO_QL 17408u
#define BO_BH 34816u
#define BO_BL 69632u
#define SMEM_BIAS 104448u

// ---------------------------------------------------------------------------
__device__ __forceinline__ uint32_t cvta_sh(const void* p) {
    uint32_t a;
    asm("{ .reg .u64 t; cvta.to.shared.u64 t, %1; cvt.u32.u64 %0, t; }"
        : "=r"(a) : "l"(p));
    return a;
}
__device__ __forceinline__ void cp16(uint32_t d, const void* s) {
    asm volatile("cp.async.ca.shared.global [%0], [%1], 16;" :: "r"(d), "l"(s));
}
#define CP_WAIT_ALL() asm volatile("cp.async.wait_all;" ::: "memory")

__device__ __forceinline__ void ldsm4(uint32_t* r, uint32_t a) {
    asm volatile("ldmatrix.sync.aligned.m8n8.x4.shared.b16 {%0,%1,%2,%3}, [%4];"
                 : "=r"(r[0]), "=r"(r[1]), "=r"(r[2]), "=r"(r[3]) : "r"(a));
}
__device__ __forceinline__ void ldsm2(uint32_t* r, uint32_t a) {
    asm volatile("ldmatrix.sync.aligned.m8n8.x2.shared.b16 {%0,%1}, [%2];"
                 : "=r"(r[0]), "=r"(r[1]) : "r"(a));
}
// NON-volatile: pure register dataflow; lets ptxas interleave independent MMAs.
__device__ __forceinline__ void mma_bf16(float* d, const uint32_t* a,
                                         uint32_t b0, uint32_t b1) {
    asm("mma.sync.aligned.m16n8k16.row.col.f32.bf16.bf16.f32 "
        "{%0,%1,%2,%3}, {%4,%5,%6,%7}, {%8,%9}, {%0,%1,%2,%3};"
        : "+f"(d[0]), "+f"(d[1]), "+f"(d[2]), "+f"(d[3])
        : "r"(a[0]), "r"(a[1]), "r"(a[2]), "r"(a[3]), "r"(b0), "r"(b1));
}

// ---------------------------------------------------------------------------
// pre-pass: Q, K (float4 path) + bias transpose
__global__ void conv_all_kernel(const float* __restrict__ Q,
                                const float* __restrict__ K,
                                const float* __restrict__ bias)
{
    const int nQ = Bz * Tz * Cz / 4;        // 524288
    const int nK = Bz * KTOT * Cz / 4;      // 1048064
    const int nB = Tz * Cz / 4;             // 32768
    int i = blockIdx.x * blockDim.x + threadIdx.x;
    if (i < nQ + nK) {
        const float4* src;
        uint2 *dh, *dl;
        int j;
        if (i < nQ) { src = (const float4*)Q; dh = (uint2*)g_Qh; dl = (uint2*)g_Ql; j = i; }
        else        { src = (const float4*)K; dh = (uint2*)g_Kh; dl = (uint2*)g_Kl; j = i - nQ; }
        float4 v = __ldg(src + j);
        __nv_bfloat162 h01 = __floats2bfloat162_rn(v.x, v.y);
        __nv_bfloat162 h23 = __floats2bfloat162_rn(v.z, v.w);
        float2 f01 = __bfloat1622float2(h01);
        float2 f23 = __bfloat1622float2(h23);
        __nv_bfloat162 l01 = __floats2bfloat162_rn(v.x - f01.x, v.y - f01.y);
        __nv_bfloat162 l23 = __floats2bfloat162_rn(v.z - f23.x, v.w - f23.y);
        uint2 h, l;
        h.x = *(uint32_t*)&h01; h.y = *(uint32_t*)&h23;
        l.x = *(uint32_t*)&l01; l.y = *(uint32_t*)&l23;
        dh[j] = h;
        dl[j] = l;
    } else if (i < nQ + nK + nB) {
        int u = i - nQ - nK;
        int o = u * 4;
        int t = o >> 7, c = o & 127;
        float4 v;
        v.x = __ldg(bias + (c + 0) * Tz + t);
        v.y = __ldg(bias + (c + 1) * Tz + t);
        v.z = __ldg(bias + (c + 2) * Tz + t);
        v.w = __ldg(bias + (c + 3) * Tz + t);
        __nv_bfloat162 h01 = __floats2bfloat162_rn(v.x, v.y);
        __nv_bfloat162 h23 = __floats2bfloat162_rn(v.z, v.w);
        float2 f01 = __bfloat1622float2(h01);
        float2 f23 = __bfloat1622float2(h23);
        __nv_bfloat162 l01 = __floats2bfloat162_rn(v.x - f01.x, v.y - f01.y);
        __nv_bfloat162 l23 = __floats2bfloat162_rn(v.z - f23.x, v.w - f23.y);
        uint2 h, l;
        h.x = *(uint32_t*)&h01; h.y = *(uint32_t*)&h23;
        l.x = *(uint32_t*)&l01; l.y = *(uint32_t*)&l23;
        ((uint2*)g_Bh)[u] = h;
        ((uint2*)g_Bl)[u] = l;
    }
}

// ---------------------------------------------------------------------------
// Kernel 1: band term. 64w x 256t strips, sliding K ring, pure Z stores.
// A register-cached per kt-half; MMAs issued pass-major across 5 n-tiles.
__global__ void __launch_bounds__(256, 2)
band_kernel(float* __restrict__ Z)
{
    extern __shared__ char sm[];
    const uint32_t sb = cvta_sh(sm);

    const int tid  = threadIdx.x;
    const int wid  = tid >> 5;
    const int lane = tid & 31;
    const int lr = lane >> 2;
    const int lc = (lane & 3) * 2;
    const int mt = wid >> 1;
    const int s  = wid & 1;

    const int b  = blockIdx.x >> 4;
    const int w0 = (blockIdx.x & 15) * 64;
    const int t0 = blockIdx.y * 256;
    const int kbase = w0 + t0;

    const char* gq_h = (const char*)g_Qh + (size_t)(b * Tz + w0) * 256;
    const char* gq_l = (const char*)g_Ql + (size_t)(b * Tz + w0) * 256;
    const char* gk_h = (const char*)g_Kh + (size_t)(b * KTOT + kbase) * 256;
    const char* gk_l = (const char*)g_Kl + (size_t)(b * KTOT + kbase) * 256;

    // zero ring slot 127 (read masked on j=0, must be finite)
    if (tid < 34) {
        uint32_t off = (tid < 17 ? OFF_KH : OFF_KL) + 127u * RST + (tid % 17) * 16;
        *(uint4*)(sm + off) = make_uint4(0, 0, 0, 0);
    }

    for (int i = tid; i < 64 * 16; i += 256) {
        int r = i >> 4, c = i & 15;
        uint32_t so = (uint32_t)r * RST + c * 16;
        size_t go = (size_t)r * 256 + c * 16;
        cp16(sb + OFF_QH + so, gq_h + go);
        cp16(sb + OFF_QL + so, gq_l + go);
    }
    for (int i = tid; i < 127 * 16; i += 256) {
        int r = i >> 4, c = i & 15;
        uint32_t so = (uint32_t)r * RST + c * 16;
        size_t go = (size_t)r * 256 + c * 16;
        cp16(sb + OFF_KH + so, gk_h + go);
        cp16(sb + OFF_KL + so, gk_l + go);
    }

    // ldmatrix lane components
    const uint32_t m8 = lane >> 3, mr = lane & 7;
    const uint32_t a_row = 16u * mt + ((m8 & 1) << 3) + mr;
    const uint32_t aH = sb + OFF_QH + a_row * RST + (m8 >> 1) * 16;
    const uint32_t aL = aH + (OFF_QL - OFF_QH);
    const int rB  = (int)((m8 >> 1) * 8 + mr);
    const uint32_t cB = (m8 & 1) * 16;
    const uint32_t l16 = lane & 15;
    const int rB2 = (int)(l16 & 7);
    const uint32_t cB2 = (l16 >> 3) * 16;

    const int gnt0 = 2 * mt + 5 * s;

    #pragma unroll 1
    for (int j = 0; j < 4; j++) {
        const int wb = 64 * j;
        float* __restrict__ Zb = Z + ((size_t)b * Tz + w0) * Tz + t0 + wb;

        CP_WAIT_ALL();
        __syncthreads();

        float acc[5][4];
        #pragma unroll
        for (int u = 0; u < 5; u++)
            #pragma unroll
            for (int e = 0; e < 4; e++) acc[u][e] = 0.0f;

        const uint32_t bb0 = sb + OFF_KH + (uint32_t)((wb + gnt0 * 8 + rB) & 127) * RST + cB;
        const uint32_t bb1 = sb + OFF_KH + (uint32_t)((wb + (gnt0 + 2) * 8 + rB) & 127) * RST + cB;
        const uint32_t bb2 = sb + OFF_KH + (uint32_t)((wb + (gnt0 + 4) * 8 + rB2) & 127) * RST + cB2;

        #pragma unroll
        for (int half = 0; half < 2; half++) {
            const uint32_t kb = (uint32_t)half * 128;    // 4 kt * 32B

            // A fragments for this half, register-cached
            uint32_t Ah[4][4], Al[4][4];
            #pragma unroll
            for (int q = 0; q < 4; q++) {
                ldsm4(Ah[q], aH + kb + q * 32);
                ldsm4(Al[q], aL + kb + q * 32);
            }

            #pragma unroll
            for (int q = 0; q < 4; q++) {
                // load all B fragments for this kt (5 n-tiles)
                uint32_t bh[10], bl[10];
                ldsm4(bh + 0, bb0 + kb + q * 32);
                ldsm4(bh + 4, bb1 + kb + q * 32);
                ldsm2(bh + 8, bb2 + kb + q * 32);
                ldsm4(bl + 0, bb0 + DHL + kb + q * 32);
                ldsm4(bl + 4, bb1 + DHL + kb + q * 32);
                ldsm2(bl + 8, bb2 + DHL + kb + q * 32);

                // pass hh: consecutive MMAs hit different accumulators
                #pragma unroll
                for (int u = 0; u < 5; u++)
                    mma_bf16(acc[u], Ah[q], bh[2 * u], bh[2 * u + 1]);
                // pass lh
                #pragma unroll
                for (int u = 0; u < 5; u++)
                    mma_bf16(acc[u], Al[q], bh[2 * u], bh[2 * u + 1]);
                // pass hl
                #pragma unroll
                for (int u = 0; u < 5; u++)
                    mma_bf16(acc[u], Ah[q], bl[2 * u], bl[2 * u + 1]);
            }
        }
        __syncthreads();                         // all ring reads complete

        // ---- prefetch next 64 K rows (rel [wb+127, wb+190]) ----
        if (j < 3) {
            for (int i = tid; i < 64 * 16; i += 256) {
                int r = i >> 4, c = i & 15;
                int rel = wb + 127 + r;
                uint32_t so = (uint32_t)(rel & 127) * RST + c * 16;
                size_t go = (size_t)rel * 256 + c * 16;
                cp16(sb + OFF_KH + so, gk_h + go);
                cp16(sb + OFF_KL + so, gk_l + go);
            }
        }

        // ---- scatter band sheared to Z (pure store; overlaps prefetch) ----
        #pragma unroll
        for (int u = 0; u < 5; u++) {
            const int n0 = (gnt0 + u) * 8 + lc;
            #pragma unroll
            for (int h = 0; h < 2; h++) {
                const int row = 16 * mt + lr + 8 * h;
                const int j0 = n0 - row;
                if ((unsigned)j0 < 64u)       Zb[(size_t)row * Tz + j0]     = acc[u][2 * h];
                if ((unsigned)(j0 + 1) < 64u) Zb[(size_t)row * Tz + j0 + 1] = acc[u][2 * h + 1];
            }
        }
    }
}

// ---------------------------------------------------------------------------
// Kernel 2: bias GEMM, Z += Q @ bias^T. 64m x 128n tiles, m32n32 warps.
// MMAs pass-major across the warp's 8 (n8 x m16) accumulator tiles.
__global__ void __launch_bounds__(256, 2)
bias_kernel(float* __restrict__ Z)
{
    extern __shared__ char sm[];
    const uint32_t sb = cvta_sh(sm);

    const int tid  = threadIdx.x;
    const int wid  = tid >> 5;
    const int lane = tid & 31;
    const int lr = lane >> 2;
    const int lc = (lane & 3) * 2;
    const int rg = wid & 1;
    const int nq = wid >> 1;

    const int m0 = blockIdx.x * 64;
    const int n0 = blockIdx.y * 128;

    const char* gq_h = (const char*)g_Qh + (size_t)m0 * 256;
    const char* gq_l = (const char*)g_Ql + (size_t)m0 * 256;
    const char* gb_h = (const char*)g_Bh + (size_t)n0 * 256;
    const char* gb_l = (const char*)g_Bl + (size_t)n0 * 256;

    for (int i = tid; i < 64 * 16; i += 256) {
        int r = i >> 4, c = i & 15;
        uint32_t so = (uint32_t)r * RST + c * 16;
        size_t go = (size_t)r * 256 + c * 16;
        cp16(sb + BO_QH + so, gq_h + go);
        cp16(sb + BO_QL + so, gq_l + go);
    }
    for (int i = tid; i < 128 * 16; i += 256) {
        int r = i >> 4, c = i & 15;
        uint32_t so = (uint32_t)r * RST + c * 16;
        size_t go = (size_t)r * 256 + c * 16;
        cp16(sb + BO_BH + so, gb_h + go);
        cp16(sb + BO_BL + so, gb_l + go);
    }
    CP_WAIT_ALL();
    __syncthreads();

    const uint32_t m8 = lane >> 3, mr = lane & 7;
    const uint32_t aH0 = sb + BO_QH + (uint32_t)(32 * rg + ((m8 & 1) << 3) + mr) * RST
                       + (m8 >> 1) * 16;
    const uint32_t aL0 = aH0 + (BO_QL - BO_QH);
    const int nB = (int)((m8 >> 1) * 8 + mr);
    const uint32_t cBy = (m8 & 1) * 16;
    const uint32_t bA0 = sb + BO_BH + (uint32_t)(32 * nq + nB) * RST + cBy;
    const uint32_t bA1 = bA0 + 16 * RST;

    float acc[4][2][4];               // [n8 tile][m16 half][4]
    #pragma unroll
    for (int u = 0; u < 4; u++)
        #pragma unroll
        for (int mh = 0; mh < 2; mh++)
            #pragma unroll
            for (int e = 0; e < 4; e++) acc[u][mh][e] = 0.0f;

    #pragma unroll
    for (int kt = 0; kt < 8; kt++) {
        uint32_t ah[2][4], al[2][4];
        ldsm4(ah[0], aH0 + kt * 32);
        ldsm4(ah[1], aH0 + 16 * RST + kt * 32);
        ldsm4(al[0], aL0 + kt * 32);
        ldsm4(al[1], aL0 + 16 * RST + kt * 32);
        uint32_t bh[8], bl[8];
        ldsm4(bh + 0, bA0 + kt * 32);
        ldsm4(bh + 4, bA1 + kt * 32);
        ldsm4(bl + 0, bA0 + (BO_BL - BO_BH) + kt * 32);
        ldsm4(bl + 4, bA1 + (BO_BL - BO_BH) + kt * 32);

        // pass hh across all 8 tiles, then lh, then hl
        #pragma unroll
        for (int u = 0; u < 4; u++)
            #pragma unroll
            for (int mh = 0; mh < 2; mh++)
                mma_bf16(acc[u][mh], ah[mh], bh[2 * u], bh[2 * u + 1]);
        #pragma unroll
        for (int u = 0; u < 4; u++)
            #pragma unroll
            for (int mh = 0; mh < 2; mh++)
                mma_bf16(acc[u][mh], al[mh], bh[2 * u], bh[2 * u + 1]);
        #pragma unroll
        for (int u = 0; u < 4; u++)
            #pragma unroll
            for (int mh = 0; mh < 2; mh++)
                mma_bf16(acc[u][mh], ah[mh], bl[2 * u], bl[2 * u + 1]);
    }

    float* __restrict__ Zb = Z + (size_t)m0 * Tz + n0;
    #pragma unroll
    for (int u = 0; u < 4; u++) {
        const int col = 32 * nq + u * 8 + lc;
        #pragma unroll
        for (int mh = 0; mh < 2; mh++)
            #pragma unroll
            for (int hh = 0; hh < 2; hh++) {
                const int row = 32 * rg + 16 * mh + 8 * hh + lr;
                float2* p = (float2*)(Zb + (size_t)row * Tz + col);
                float2 z = *p;
                z.x += acc[u][mh][2 * hh];
                z.y += acc[u][mh][2 * hh + 1];
                *p = z;
            }
    }
}

// ---------------------------------------------------------------------------
extern "C" void kernel_launch(void* const* d_in, const int* in_sizes, int n_in,
                              void* d_out, int out_size)
{
    const float* Q    = (const float*)d_in[0];   // (16, 1024, 128)
    const float* K    = (const float*)d_in[1];   // (16, 2047, 128)
    const float* bias = (const float*)d_in[2];   // (128, 1024)
    float* Z = (float*)d_out;                    // (16, 1024, 1024)

    static int configured = 0;
    if (!configured) {
        cudaFuncSetAttribute(band_kernel,
                             cudaFuncAttributeMaxDynamicSharedMemorySize, SMEM_BAND);
        cudaFuncSetAttribute(bias_kernel,
                             cudaFuncAttributeMaxDynamicSharedMemorySize, SMEM_BIAS);
        configured = 1;
    }

    conv_all_kernel<<<6270, 256>>>(Q, K, bias);

    dim3 bgrid(256, 4, 1);              // x = b*16 + w-strip, y = t-strip
    band_kernel<<<bgrid, 256, SMEM_BAND>>>(Z);

    dim3 pgrid(256, 8, 1);              // x = m-tile (64 rows), y = n-tile (128 cols)
    bias_kernel<<<pgrid, 256, SMEM_BIAS>>>(Z);
}

// round 12
// speedup vs baseline: 1.4377x; 1.4377x over previous
#include <cuda_runtime.h>
#include <cuda_bf16.h>
#include <stdint.h>

// SlidingWindowMatrixMult3D via mma.sync bf16, 3-pass fp32 emulation.
// Z[b,w,t] = sum_c Q[b,w,c]*K[b,w+t,c] + sum_c Q[b,w,c]*bias[c,t]
// B=16, T=1024, C=128.
//
// R12: revert to R9 (133.1us known-good; volatile MMAs, bounded live ranges),
// plus register-neutral accumulator-pair interleave (RAW distance 2 instead
// of 1) in both MMA loops. R10/R11's wide pass-major scheme spilled; this
// keeps R9's exact live set.

#define Bz 16
#define Tz 1024
#define Cz 128
#define KTOT 2047
#define KPADROWS 128

// ---- global bf16 scratch ----
__device__ __nv_bfloat16 g_Qh[Bz * Tz * Cz];
__device__ __nv_bfloat16 g_Ql[Bz * Tz * Cz];
__device__ __nv_bfloat16 g_Kh[(Bz * KTOT + KPADROWS) * Cz];
__device__ __nv_bfloat16 g_Kl[(Bz * KTOT + KPADROWS) * Cz];
__device__ __nv_bfloat16 g_Bh[Tz * Cz];     // transposed: [t][c]
__device__ __nv_bfloat16 g_Bl[Tz * Cz];

// ---- shared layouts (both kernels 102 KB -> 2 CTA/SM) ----
#define RST 272u
#define OFF_QH 0u
#define OFF_QL 17408u
#define OFF_KH 34816u            // 128-slot ring (hi)
#define OFF_KL 69632u            // 128-slot ring (lo)
#define DHL    34816u            // hi -> lo delta
#define SMEM_BAND 104448u
#define BO_QH 0u
#define BO_QL 17408u
#define BO_BH 34816u
#define BO_BL 69632u
#define SMEM_BIAS 104448u

// ---------------------------------------------------------------------------
__device__ __forceinline__ uint32_t cvta_sh(const void* p) {
    uint32_t a;
    asm("{ .reg .u64 t; cvta.to.shared.u64 t, %1; cvt.u32.u64 %0, t; }"
        : "=r"(a) : "l"(p));
    return a;
}
__device__ __forceinline__ void cp16(uint32_t d, const void* s) {
    asm volatile("cp.async.ca.shared.global [%0], [%1], 16;" :: "r"(d), "l"(s));
}
#define CP_WAIT_ALL() asm volatile("cp.async.wait_all;" ::: "memory")

__device__ __forceinline__ void ldsm4(uint32_t* r, uint32_t a) {
    asm volatile("ldmatrix.sync.aligned.m8n8.x4.shared.b16 {%0,%1,%2,%3}, [%4];"
                 : "=r"(r[0]), "=r"(r[1]), "=r"(r[2]), "=r"(r[3]) : "r"(a));
}
__device__ __forceinline__ void ldsm2(uint32_t* r, uint32_t a) {
    asm volatile("ldmatrix.sync.aligned.m8n8.x2.shared.b16 {%0,%1}, [%2];"
                 : "=r"(r[0]), "=r"(r[1]) : "r"(a));
}
// volatile: fixed issue order; keeps ptxas live ranges bounded (R11 lesson).
__device__ __forceinline__ void mma_bf16(float* d, const uint32_t* a,
                                         uint32_t b0, uint32_t b1) {
    asm volatile(
        "mma.sync.aligned.m16n8k16.row.col.f32.bf16.bf16.f32 "
        "{%0,%1,%2,%3}, {%4,%5,%6,%7}, {%8,%9}, {%0,%1,%2,%3};"
        : "+f"(d[0]), "+f"(d[1]), "+f"(d[2]), "+f"(d[3])
        : "r"(a[0]), "r"(a[1]), "r"(a[2]), "r"(a[3]), "r"(b0), "r"(b1));
}
// serial 3-pass on one accumulator (lone tiles)
__device__ __forceinline__ void mma3(float* d, const uint32_t* ah, const uint32_t* al,
                                     uint32_t bh0, uint32_t bh1,
                                     uint32_t bl0, uint32_t bl1) {
    mma_bf16(d, ah, bh0, bh1);
    mma_bf16(d, al, bh0, bh1);
    mma_bf16(d, ah, bl0, bl1);
}
// interleaved 3-pass over an accumulator pair: same A, two B n8-tiles
__device__ __forceinline__ void mma3x2B(float* d0, float* d1,
                                        const uint32_t* ah, const uint32_t* al,
                                        const uint32_t* bh, const uint32_t* bl) {
    mma_bf16(d0, ah, bh[0], bh[1]);
    mma_bf16(d1, ah, bh[2], bh[3]);
    mma_bf16(d0, al, bh[0], bh[1]);
    mma_bf16(d1, al, bh[2], bh[3]);
    mma_bf16(d0, ah, bl[0], bl[1]);
    mma_bf16(d1, ah, bl[2], bl[3]);
}
// interleaved 3-pass over an accumulator pair: same B, two A m16-tiles
__device__ __forceinline__ void mma3x2A(float* d0, float* d1,
                                        const uint32_t* ah0, const uint32_t* al0,
                                        const uint32_t* ah1, const uint32_t* al1,
                                        uint32_t bh0, uint32_t bh1,
                                        uint32_t bl0, uint32_t bl1) {
    mma_bf16(d0, ah0, bh0, bh1);
    mma_bf16(d1, ah1, bh0, bh1);
    mma_bf16(d0, al0, bh0, bh1);
    mma_bf16(d1, al1, bh0, bh1);
    mma_bf16(d0, ah0, bl0, bl1);
    mma_bf16(d1, ah1, bl0, bl1);
}

// ---------------------------------------------------------------------------
// pre-pass: Q, K (float4 path) + bias transpose
__global__ void conv_all_kernel(const float* __restrict__ Q,
                                const float* __restrict__ K,
                                const float* __restrict__ bias)
{
    const int nQ = Bz * Tz * Cz / 4;        // 524288
    const int nK = Bz * KTOT * Cz / 4;      // 1048064
    const int nB = Tz * Cz / 4;             // 32768
    int i = blockIdx.x * blockDim.x + threadIdx.x;
    if (i < nQ + nK) {
        const float4* src;
        uint2 *dh, *dl;
        int j;
        if (i < nQ) { src = (const float4*)Q; dh = (uint2*)g_Qh; dl = (uint2*)g_Ql; j = i; }
        else        { src = (const float4*)K; dh = (uint2*)g_Kh; dl = (uint2*)g_Kl; j = i - nQ; }
        float4 v = __ldg(src + j);
        __nv_bfloat162 h01 = __floats2bfloat162_rn(v.x, v.y);
        __nv_bfloat162 h23 = __floats2bfloat162_rn(v.z, v.w);
        float2 f01 = __bfloat1622float2(h01);
        float2 f23 = __bfloat1622float2(h23);
        __nv_bfloat162 l01 = __floats2bfloat162_rn(v.x - f01.x, v.y - f01.y);
        __nv_bfloat162 l23 = __floats2bfloat162_rn(v.z - f23.x, v.w - f23.y);
        uint2 h, l;
        h.x = *(uint32_t*)&h01; h.y = *(uint32_t*)&h23;
        l.x = *(uint32_t*)&l01; l.y = *(uint32_t*)&l23;
        dh[j] = h;
        dl[j] = l;
    } else if (i < nQ + nK + nB) {
        int u = i - nQ - nK;
        int o = u * 4;
        int t = o >> 7, c = o & 127;
        float4 v;
        v.x = __ldg(bias + (c + 0) * Tz + t);
        v.y = __ldg(bias + (c + 1) * Tz + t);
        v.z = __ldg(bias + (c + 2) * Tz + t);
        v.w = __ldg(bias + (c + 3) * Tz + t);
        __nv_bfloat162 h01 = __floats2bfloat162_rn(v.x, v.y);
        __nv_bfloat162 h23 = __floats2bfloat162_rn(v.z, v.w);
        float2 f01 = __bfloat1622float2(h01);
        float2 f23 = __bfloat1622float2(h23);
        __nv_bfloat162 l01 = __floats2bfloat162_rn(v.x - f01.x, v.y - f01.y);
        __nv_bfloat162 l23 = __floats2bfloat162_rn(v.z - f23.x, v.w - f23.y);
        uint2 h, l;
        h.x = *(uint32_t*)&h01; h.y = *(uint32_t*)&h23;
        l.x = *(uint32_t*)&l01; l.y = *(uint32_t*)&l23;
        ((uint2*)g_Bh)[u] = h;
        ((uint2*)g_Bl)[u] = l;
    }
}

// ---------------------------------------------------------------------------
// Kernel 1: band term. 64w x 256t strips, sliding K ring, pure Z stores.
// A register-cached per kt-half; B double-buffered per n16 group (R9 layout);
// accumulator pairs interleaved (RAW distance 2).
__global__ void __launch_bounds__(256, 2)
band_kernel(float* __restrict__ Z)
{
    extern __shared__ char sm[];
    const uint32_t sb = cvta_sh(sm);

    const int tid  = threadIdx.x;
    const int wid  = tid >> 5;
    const int lane = tid & 31;
    const int lr = lane >> 2;
    const int lc = (lane & 3) * 2;
    const int mt = wid >> 1;
    const int s  = wid & 1;

    const int b  = blockIdx.x >> 4;
    const int w0 = (blockIdx.x & 15) * 64;
    const int t0 = blockIdx.y * 256;
    const int kbase = w0 + t0;

    const char* gq_h = (const char*)g_Qh + (size_t)(b * Tz + w0) * 256;
    const char* gq_l = (const char*)g_Ql + (size_t)(b * Tz + w0) * 256;
    const char* gk_h = (const char*)g_Kh + (size_t)(b * KTOT + kbase) * 256;
    const char* gk_l = (const char*)g_Kl + (size_t)(b * KTOT + kbase) * 256;

    // zero ring slot 127 (read masked on j=0, must be finite)
    if (tid < 34) {
        uint32_t off = (tid < 17 ? OFF_KH : OFF_KL) + 127u * RST + (tid % 17) * 16;
        *(uint4*)(sm + off) = make_uint4(0, 0, 0, 0);
    }

    for (int i = tid; i < 64 * 16; i += 256) {
        int r = i >> 4, c = i & 15;
        uint32_t so = (uint32_t)r * RST + c * 16;
        size_t go = (size_t)r * 256 + c * 16;
        cp16(sb + OFF_QH + so, gq_h + go);
        cp16(sb + OFF_QL + so, gq_l + go);
    }
    for (int i = tid; i < 127 * 16; i += 256) {
        int r = i >> 4, c = i & 15;
        uint32_t so = (uint32_t)r * RST + c * 16;
        size_t go = (size_t)r * 256 + c * 16;
        cp16(sb + OFF_KH + so, gk_h + go);
        cp16(sb + OFF_KL + so, gk_l + go);
    }

    // ldmatrix lane components
    const uint32_t m8 = lane >> 3, mr = lane & 7;
    const uint32_t a_row = 16u * mt + ((m8 & 1) << 3) + mr;
    const uint32_t aH = sb + OFF_QH + a_row * RST + (m8 >> 1) * 16;
    const uint32_t aL = aH + (OFF_QL - OFF_QH);
    const int rB  = (int)((m8 >> 1) * 8 + mr);
    const uint32_t cB = (m8 & 1) * 16;
    const uint32_t l16 = lane & 15;
    const int rB2 = (int)(l16 & 7);
    const uint32_t cB2 = (l16 >> 3) * 16;

    const int gnt0 = 2 * mt + 5 * s;

    #pragma unroll 1
    for (int j = 0; j < 4; j++) {
        const int wb = 64 * j;
        float* __restrict__ Zb = Z + ((size_t)b * Tz + w0) * Tz + t0 + wb;

        CP_WAIT_ALL();
        __syncthreads();

        float acc[5][4];
        #pragma unroll
        for (int u = 0; u < 5; u++)
            #pragma unroll
            for (int e = 0; e < 4; e++) acc[u][e] = 0.0f;

        const uint32_t bb0 = sb + OFF_KH + (uint32_t)((wb + gnt0 * 8 + rB) & 127) * RST + cB;
        const uint32_t bb1 = sb + OFF_KH + (uint32_t)((wb + (gnt0 + 2) * 8 + rB) & 127) * RST + cB;
        const uint32_t bb2 = sb + OFF_KH + (uint32_t)((wb + (gnt0 + 4) * 8 + rB2) & 127) * RST + cB2;

        #pragma unroll
        for (int half = 0; half < 2; half++) {
            const uint32_t kb = (uint32_t)half * 128;    // 4 kt * 32B

            // A fragments for this half, register-cached
            uint32_t Ah[4][4], Al[4][4];
            #pragma unroll
            for (int q = 0; q < 4; q++) {
                ldsm4(Ah[q], aH + kb + q * 32);
                ldsm4(Al[q], aL + kb + q * 32);
            }

            // ---- group 0: n16 pair (gnt0, gnt0+1), B double-buffered ----
            {
                uint32_t bh[2][4], bl[2][4];
                ldsm4(bh[0], bb0 + kb);
                ldsm4(bl[0], bb0 + DHL + kb);
                #pragma unroll
                for (int q = 0; q < 4; q++) {
                    const int cur = q & 1, nxt = cur ^ 1;
                    if (q < 3) {
                        ldsm4(bh[nxt], bb0 + kb + (q + 1) * 32);
                        ldsm4(bl[nxt], bb0 + DHL + kb + (q + 1) * 32);
                    }
                    mma3x2B(acc[0], acc[1], Ah[q], Al[q], bh[cur], bl[cur]);
                }
            }
            // ---- group 1: n16 pair (gnt0+2, gnt0+3) ----
            {
                uint32_t bh[2][4], bl[2][4];
                ldsm4(bh[0], bb1 + kb);
                ldsm4(bl[0], bb1 + DHL + kb);
                #pragma unroll
                for (int q = 0; q < 4; q++) {
                    const int cur = q & 1, nxt = cur ^ 1;
                    if (q < 3) {
                        ldsm4(bh[nxt], bb1 + kb + (q + 1) * 32);
                        ldsm4(bl[nxt], bb1 + DHL + kb + (q + 1) * 32);
                    }
                    mma3x2B(acc[2], acc[3], Ah[q], Al[q], bh[cur], bl[cur]);
                }
            }
            // ---- group 2: lone n8 tile (gnt0+4) via ldsm2 ----
            {
                uint32_t bh[2][2], bl[2][2];
                ldsm2(bh[0], bb2 + kb);
                ldsm2(bl[0], bb2 + DHL + kb);
                #pragma unroll
                for (int q = 0; q < 4; q++) {
                    const int cur = q & 1, nxt = cur ^ 1;
                    if (q < 3) {
                        ldsm2(bh[nxt], bb2 + kb + (q + 1) * 32);
                        ldsm2(bl[nxt], bb2 + DHL + kb + (q + 1) * 32);
                    }
                    mma3(acc[4], Ah[q], Al[q], bh[cur][0], bh[cur][1], bl[cur][0], bl[cur][1]);
                }
            }
        }
        __syncthreads();                         // all ring reads complete

        // ---- prefetch next 64 K rows (rel [wb+127, wb+190]) ----
        if (j < 3) {
            for (int i = tid; i < 64 * 16; i += 256) {
                int r = i >> 4, c = i & 15;
                int rel = wb + 127 + r;
                uint32_t so = (uint32_t)(rel & 127) * RST + c * 16;
                size_t go = (size_t)rel * 256 + c * 16;
                cp16(sb + OFF_KH + so, gk_h + go);
                cp16(sb + OFF_KL + so, gk_l + go);
            }
        }

        // ---- scatter band sheared to Z (pure store; overlaps prefetch) ----
        #pragma unroll
        for (int u = 0; u < 5; u++) {
            const int n0 = (gnt0 + u) * 8 + lc;
            #pragma unroll
            for (int h = 0; h < 2; h++) {
                const int row = 16 * mt + lr + 8 * h;
                const int j0 = n0 - row;
                if ((unsigned)j0 < 64u)       Zb[(size_t)row * Tz + j0]     = acc[u][2 * h];
                if ((unsigned)(j0 + 1) < 64u) Zb[(size_t)row * Tz + j0 + 1] = acc[u][2 * h + 1];
            }
        }
    }
}

// ---------------------------------------------------------------------------
// Kernel 2: bias GEMM, Z += Q @ bias^T. 64m x 128n tiles, m32n32 warps.
// Accumulator m16-pairs interleaved (RAW distance 2).
__global__ void __launch_bounds__(256, 2)
bias_kernel(float* __restrict__ Z)
{
    extern __shared__ char sm[];
    const uint32_t sb = cvta_sh(sm);

    const int tid  = threadIdx.x;
    const int wid  = tid >> 5;
    const int lane = tid & 31;
    const int lr = lane >> 2;
    const int lc = (lane & 3) * 2;
    const int rg = wid & 1;
    const int nq = wid >> 1;

    const int m0 = blockIdx.x * 64;
    const int n0 = blockIdx.y * 128;

    const char* gq_h = (const char*)g_Qh + (size_t)m0 * 256;
    const char* gq_l = (const char*)g_Ql + (size_t)m0 * 256;
    const char* gb_h = (const char*)g_Bh + (size_t)n0 * 256;
    const char* gb_l = (const char*)g_Bl + (size_t)n0 * 256;

    for (int i = tid; i < 64 * 16; i += 256) {
        int r = i >> 4, c = i & 15;
        uint32_t so = (uint32_t)r * RST + c * 16;
        size_t go = (size_t)r * 256 + c * 16;
        cp16(sb + BO_QH + so, gq_h + go);
        cp16(sb + BO_QL + so, gq_l + go);
    }
    for (int i = tid; i < 128 * 16; i += 256) {
        int r = i >> 4, c = i & 15;
        uint32_t so = (uint32_t)r * RST + c * 16;
        size_t go = (size_t)r * 256 + c * 16;
        cp16(sb + BO_BH + so, gb_h + go);
        cp16(sb + BO_BL + so, gb_l + go);
    }
    CP_WAIT_ALL();
    __syncthreads();

    const uint32_t m8 = lane >> 3, mr = lane & 7;
    const uint32_t aH0 = sb + BO_QH + (uint32_t)(32 * rg + ((m8 & 1) << 3) + mr) * RST
                       + (m8 >> 1) * 16;
    const uint32_t aL0 = aH0 + (BO_QL - BO_QH);
    const int nB = (int)((m8 >> 1) * 8 + mr);
    const uint32_t cBy = (m8 & 1) * 16;
    const uint32_t bA0 = sb + BO_BH + (uint32_t)(32 * nq + nB) * RST + cBy;
    const uint32_t bA1 = bA0 + 16 * RST;

    float acc[4][2][4];
    #pragma unroll
    for (int u = 0; u < 4; u++)
        #pragma unroll
        for (int mh = 0; mh < 2; mh++)
            #pragma unroll
            for (int e = 0; e < 4; e++) acc[u][mh][e] = 0.0f;

    #pragma unroll 1
    for (int kt = 0; kt < 8; kt++) {
        uint32_t ah0[4], ah1[4], al0[4], al1[4];
        ldsm4(ah0, aH0 + kt * 32);
        ldsm4(ah1, aH0 + 16 * RST + kt * 32);
        ldsm4(al0, aL0 + kt * 32);
        ldsm4(al1, aL0 + 16 * RST + kt * 32);
        uint32_t bh[4], bl[4];
        ldsm4(bh, bA0 + kt * 32);
        ldsm4(bl, bA0 + (BO_BL - BO_BH) + kt * 32);
        mma3x2A(acc[0][0], acc[0][1], ah0, al0, ah1, al1, bh[0], bh[1], bl[0], bl[1]);
        mma3x2A(acc[1][0], acc[1][1], ah0, al0, ah1, al1, bh[2], bh[3], bl[2], bl[3]);
        ldsm4(bh, bA1 + kt * 32);
        ldsm4(bl, bA1 + (BO_BL - BO_BH) + kt * 32);
        mma3x2A(acc[2][0], acc[2][1], ah0, al0, ah1, al1, bh[0], bh[1], bl[0], bl[1]);
        mma3x2A(acc[3][0], acc[3][1], ah0, al0, ah1, al1, bh[2], bh[3], bl[2], bl[3]);
    }

    float* __restrict__ Zb = Z + (size_t)m0 * Tz + n0;
    #pragma unroll
    for (int u = 0; u < 4; u++) {
        const int col = 32 * nq + u * 8 + lc;
        #pragma unroll
        for (int mh = 0; mh < 2; mh++)
            #pragma unroll
            for (int hh = 0; hh < 2; hh++) {
                const int row = 32 * rg + 16 * mh + 8 * hh + lr;
                float2* p = (float2*)(Zb + (size_t)row * Tz + col);
                float2 z = *p;
                z.x += acc[u][mh][2 * hh];
                z.y += acc[u][mh][2 * hh + 1];
                *p = z;
            }
    }
}

// ---------------------------------------------------------------------------
extern "C" void kernel_launch(void* const* d_in, const int* in_sizes, int n_in,
                              void* d_out, int out_size)
{
    const float* Q    = (const float*)d_in[0];   // (16, 1024, 128)
    const float* K    = (const float*)d_in[1];   // (16, 2047, 128)
    const float* bias = (const float*)d_in[2];   // (128, 1024)
    float* Z = (float*)d_out;                    // (16, 1024, 1024)

    static int configured = 0;
    if (!configured) {
        cudaFuncSetAttribute(band_kernel,
                             cudaFuncAttributeMaxDynamicSharedMemorySize, SMEM_BAND);
        cudaFuncSetAttribute(bias_kernel,
                             cudaFuncAttributeMaxDynamicSharedMemorySize, SMEM_BIAS);
        configured = 1;
    }

    conv_all_kernel<<<6270, 256>>>(Q, K, bias);

    dim3 bgrid(256, 4, 1);              // x = b*16 + w-strip, y = t-strip
    band_kernel<<<bgrid, 256, SMEM_BAND>>>(Z);

    dim3 pgrid(256, 8, 1);              // x = m-tile (64 rows), y = n-tile (128 cols)
    bias_kernel<<<pgrid, 256, SMEM_BIAS>>>(Z);
}

// round 13
// speedup vs baseline: 1.9926x; 1.3859x over previous
#include <cuda_runtime.h>
#include <cuda_fp16.h>
#include <stdint.h>

// SlidingWindowMatrixMult3D via mma.sync fp16 (single pass, fp32 accumulate).
// Z[b,w,t] = sum_c Q[b,w,c]*K[b,w+t,c] + sum_c Q[b,w,c]*bias[c,t]
// B=16, T=1024, C=128.
//
// R13: drop the bf16 hi/lo 3-pass emulation for single-pass fp16.
// Error model (norm metric, verified by R12's rel_err matching prediction):
// ~2*2^-11 input rounding -> rel_err ~3-5e-4 < 1e-3 threshold.
// MMA count /3, smem /2 (52KB -> 3-4 CTA/SM), conv traffic /2.

#define Bz 16
#define Tz 1024
#define Cz 128
#define KTOT 2047
#define KPADROWS 128

// ---- global fp16 scratch ----
__device__ __half g_Qm[Bz * Tz * Cz];
__device__ __half g_Km[(Bz * KTOT + KPADROWS) * Cz];
__device__ __half g_Bm[Tz * Cz];     // transposed: [t][c]

// ---- shared layouts: rows of 128 fp16 (256B) padded to 272B ----
#define RST 272u
// band: Q 64 rows + 128-slot K ring = 17408 + 34816 = 52224 B -> 3 CTA/SM
#define OFF_Q 0u
#define OFF_K 17408u
#define SMEM_BAND 52224u
// bias: Q 64 rows + bias 128 rows = 52224 B -> 3-4 CTA/SM
#define BO_Q 0u
#define BO_B 17408u
#define SMEM_BIAS 52224u

// ---------------------------------------------------------------------------
__device__ __forceinline__ uint32_t cvta_sh(const void* p) {
    uint32_t a;
    asm("{ .reg .u64 t; cvta.to.shared.u64 t, %1; cvt.u32.u64 %0, t; }"
        : "=r"(a) : "l"(p));
    return a;
}
__device__ __forceinline__ void cp16(uint32_t d, const void* s) {
    asm volatile("cp.async.ca.shared.global [%0], [%1], 16;" :: "r"(d), "l"(s));
}
#define CP_WAIT_ALL() asm volatile("cp.async.wait_all;" ::: "memory")

__device__ __forceinline__ void ldsm4(uint32_t* r, uint32_t a) {
    asm volatile("ldmatrix.sync.aligned.m8n8.x4.shared.b16 {%0,%1,%2,%3}, [%4];"
                 : "=r"(r[0]), "=r"(r[1]), "=r"(r[2]), "=r"(r[3]) : "r"(a));
}
__device__ __forceinline__ void ldsm2(uint32_t* r, uint32_t a) {
    asm volatile("ldmatrix.sync.aligned.m8n8.x2.shared.b16 {%0,%1}, [%2];"
                 : "=r"(r[0]), "=r"(r[1]) : "r"(a));
}
// fp16 inputs, fp32 accumulate. volatile: bounded live ranges (R11 lesson).
__device__ __forceinline__ void mma_f16(float* d, const uint32_t* a,
                                        uint32_t b0, uint32_t b1) {
    asm volatile(
        "mma.sync.aligned.m16n8k16.row.col.f32.f16.f16.f32 "
        "{%0,%1,%2,%3}, {%4,%5,%6,%7}, {%8,%9}, {%0,%1,%2,%3};"
        : "+f"(d[0]), "+f"(d[1]), "+f"(d[2]), "+f"(d[3])
        : "r"(a[0]), "r"(a[1]), "r"(a[2]), "r"(a[3]), "r"(b0), "r"(b1));
}

// ---------------------------------------------------------------------------
// pre-pass: Q, K (float4 path) + bias transpose -> fp16
__global__ void conv_all_kernel(const float* __restrict__ Q,
                                const float* __restrict__ K,
                                const float* __restrict__ bias)
{
    const int nQ = Bz * Tz * Cz / 4;        // 524288
    const int nK = Bz * KTOT * Cz / 4;      // 1048064
    const int nB = Tz * Cz / 4;             // 32768
    int i = blockIdx.x * blockDim.x + threadIdx.x;
    if (i < nQ + nK) {
        const float4* src;
        uint2* dst;
        int j;
        if (i < nQ) { src = (const float4*)Q; dst = (uint2*)g_Qm; j = i; }
        else        { src = (const float4*)K; dst = (uint2*)g_Km; j = i - nQ; }
        float4 v = __ldg(src + j);
        __half2 h01 = __floats2half2_rn(v.x, v.y);
        __half2 h23 = __floats2half2_rn(v.z, v.w);
        uint2 h;
        h.x = *(uint32_t*)&h01; h.y = *(uint32_t*)&h23;
        dst[j] = h;
    } else if (i < nQ + nK + nB) {
        int u = i - nQ - nK;
        int o = u * 4;
        int t = o >> 7, c = o & 127;
        float4 v;
        v.x = __ldg(bias + (c + 0) * Tz + t);
        v.y = __ldg(bias + (c + 1) * Tz + t);
        v.z = __ldg(bias + (c + 2) * Tz + t);
        v.w = __ldg(bias + (c + 3) * Tz + t);
        __half2 h01 = __floats2half2_rn(v.x, v.y);
        __half2 h23 = __floats2half2_rn(v.z, v.w);
        uint2 h;
        h.x = *(uint32_t*)&h01; h.y = *(uint32_t*)&h23;
        ((uint2*)g_Bm)[u] = h;
    }
}

// ---------------------------------------------------------------------------
// Kernel 1: band term. 64w x 256t strips, sliding 128-row K ring, pure Z
// stores. A register-cached per kt-half; single fp16 pass.
__global__ void __launch_bounds__(256, 3)
band_kernel(float* __restrict__ Z)
{
    extern __shared__ char sm[];
    const uint32_t sb = cvta_sh(sm);

    const int tid  = threadIdx.x;
    const int wid  = tid >> 5;
    const int lane = tid & 31;
    const int lr = lane >> 2;
    const int lc = (lane & 3) * 2;
    const int mt = wid >> 1;
    const int s  = wid & 1;

    const int b  = blockIdx.x >> 4;
    const int w0 = (blockIdx.x & 15) * 64;
    const int t0 = blockIdx.y * 256;
    const int kbase = w0 + t0;

    const char* gq = (const char*)g_Qm + (size_t)(b * Tz + w0) * 256;
    const char* gk = (const char*)g_Km + (size_t)(b * KTOT + kbase) * 256;

    // zero ring slot 127 (read masked on j=0, must be finite)
    if (tid < 17) {
        *(uint4*)(sm + OFF_K + 127u * RST + tid * 16) = make_uint4(0, 0, 0, 0);
    }

    for (int i = tid; i < 64 * 16; i += 256) {
        int r = i >> 4, c = i & 15;
        cp16(sb + OFF_Q + (uint32_t)r * RST + c * 16, gq + (size_t)r * 256 + c * 16);
    }
    for (int i = tid; i < 127 * 16; i += 256) {
        int r = i >> 4, c = i & 15;
        cp16(sb + OFF_K + (uint32_t)r * RST + c * 16, gk + (size_t)r * 256 + c * 16);
    }

    // ldmatrix lane components
    const uint32_t m8 = lane >> 3, mr = lane & 7;
    const uint32_t a_row = 16u * mt + ((m8 & 1) << 3) + mr;
    const uint32_t aA = sb + OFF_Q + a_row * RST + (m8 >> 1) * 16;
    const int rB  = (int)((m8 >> 1) * 8 + mr);
    const uint32_t cB = (m8 & 1) * 16;
    const uint32_t l16 = lane & 15;
    const int rB2 = (int)(l16 & 7);
    const uint32_t cB2 = (l16 >> 3) * 16;

    const int gnt0 = 2 * mt + 5 * s;

    #pragma unroll 1
    for (int j = 0; j < 4; j++) {
        const int wb = 64 * j;
        float* __restrict__ Zb = Z + ((size_t)b * Tz + w0) * Tz + t0 + wb;

        CP_WAIT_ALL();
        __syncthreads();

        float acc[5][4];
        #pragma unroll
        for (int u = 0; u < 5; u++)
            #pragma unroll
            for (int e = 0; e < 4; e++) acc[u][e] = 0.0f;

        const uint32_t bb0 = sb + OFF_K + (uint32_t)((wb + gnt0 * 8 + rB) & 127) * RST + cB;
        const uint32_t bb1 = sb + OFF_K + (uint32_t)((wb + (gnt0 + 2) * 8 + rB) & 127) * RST + cB;
        const uint32_t bb2 = sb + OFF_K + (uint32_t)((wb + (gnt0 + 4) * 8 + rB2) & 127) * RST + cB2;

        #pragma unroll
        for (int half = 0; half < 2; half++) {
            const uint32_t kb = (uint32_t)half * 128;    // 4 kt * 32B

            // A fragments for this half, register-cached
            uint32_t A[4][4];
            #pragma unroll
            for (int q = 0; q < 4; q++)
                ldsm4(A[q], aA + kb + q * 32);

            #pragma unroll
            for (int q = 0; q < 4; q++) {
                uint32_t b01[4], b23[4], b4[2];
                ldsm4(b01, bb0 + kb + q * 32);
                ldsm4(b23, bb1 + kb + q * 32);
                ldsm2(b4,  bb2 + kb + q * 32);
                mma_f16(acc[0], A[q], b01[0], b01[1]);
                mma_f16(acc[1], A[q], b01[2], b01[3]);
                mma_f16(acc[2], A[q], b23[0], b23[1]);
                mma_f16(acc[3], A[q], b23[2], b23[3]);
                mma_f16(acc[4], A[q], b4[0],  b4[1]);
            }
        }
        __syncthreads();                         // all ring reads complete

        // ---- prefetch next 64 K rows (rel [wb+127, wb+190]) ----
        if (j < 3) {
            for (int i = tid; i < 64 * 16; i += 256) {
                int r = i >> 4, c = i & 15;
                int rel = wb + 127 + r;
                cp16(sb + OFF_K + (uint32_t)(rel & 127) * RST + c * 16,
                     gk + (size_t)rel * 256 + c * 16);
            }
        }

        // ---- scatter band sheared to Z (pure store; overlaps prefetch) ----
        #pragma unroll
        for (int u = 0; u < 5; u++) {
            const int n0 = (gnt0 + u) * 8 + lc;
            #pragma unroll
            for (int h = 0; h < 2; h++) {
                const int row = 16 * mt + lr + 8 * h;
                const int j0 = n0 - row;
                if ((unsigned)j0 < 64u)       Zb[(size_t)row * Tz + j0]     = acc[u][2 * h];
                if ((unsigned)(j0 + 1) < 64u) Zb[(size_t)row * Tz + j0 + 1] = acc[u][2 * h + 1];
            }
        }
    }
}

// ---------------------------------------------------------------------------
// Kernel 2: bias GEMM, Z += Q @ bias^T. 64m x 128n tiles, m32n32 warps,
// single fp16 pass, RMW epilogue.
__global__ void __launch_bounds__(256, 4)
bias_kernel(float* __restrict__ Z)
{
    extern __shared__ char sm[];
    const uint32_t sb = cvta_sh(sm);

    const int tid  = threadIdx.x;
    const int wid  = tid >> 5;
    const int lane = tid & 31;
    const int lr = lane >> 2;
    const int lc = (lane & 3) * 2;
    const int rg = wid & 1;
    const int nq = wid >> 1;

    const int m0 = blockIdx.x * 64;
    const int n0 = blockIdx.y * 128;

    const char* gq = (const char*)g_Qm + (size_t)m0 * 256;
    const char* gb = (const char*)g_Bm + (size_t)n0 * 256;

    for (int i = tid; i < 64 * 16; i += 256) {
        int r = i >> 4, c = i & 15;
        cp16(sb + BO_Q + (uint32_t)r * RST + c * 16, gq + (size_t)r * 256 + c * 16);
    }
    for (int i = tid; i < 128 * 16; i += 256) {
        int r = i >> 4, c = i & 15;
        cp16(sb + BO_B + (uint32_t)r * RST + c * 16, gb + (size_t)r * 256 + c * 16);
    }
    CP_WAIT_ALL();
    __syncthreads();

    const uint32_t m8 = lane >> 3, mr = lane & 7;
    const uint32_t aA0 = sb + BO_Q + (uint32_t)(32 * rg + ((m8 & 1) << 3) + mr) * RST
                       + (m8 >> 1) * 16;
    const int nB = (int)((m8 >> 1) * 8 + mr);
    const uint32_t cBy = (m8 & 1) * 16;
    const uint32_t bA0 = sb + BO_B + (uint32_t)(32 * nq + nB) * RST + cBy;
    const uint32_t bA1 = bA0 + 16 * RST;

    float acc[4][2][4];               // [n8 tile][m16 half][4]
    #pragma unroll
    for (int u = 0; u < 4; u++)
        #pragma unroll
        for (int mh = 0; mh < 2; mh++)
            #pragma unroll
            for (int e = 0; e < 4; e++) acc[u][mh][e] = 0.0f;

    #pragma unroll
    for (int kt = 0; kt < 8; kt++) {
        uint32_t a0[4], a1[4];
        ldsm4(a0, aA0 + kt * 32);
        ldsm4(a1, aA0 + 16 * RST + kt * 32);
        uint32_t bh[4];
        ldsm4(bh, bA0 + kt * 32);
        mma_f16(acc[0][0], a0, bh[0], bh[1]);
        mma_f16(acc[0][1], a1, bh[0], bh[1]);
        mma_f16(acc[1][0], a0, bh[2], bh[3]);
        mma_f16(acc[1][1], a1, bh[2], bh[3]);
        ldsm4(bh, bA1 + kt * 32);
        mma_f16(acc[2][0], a0, bh[0], bh[1]);
        mma_f16(acc[2][1], a1, bh[0], bh[1]);
        mma_f16(acc[3][0], a0, bh[2], bh[3]);
        mma_f16(acc[3][1], a1, bh[2], bh[3]);
    }

    float* __restrict__ Zb = Z + (size_t)m0 * Tz + n0;
    #pragma unroll
    for (int u = 0; u < 4; u++) {
        const int col = 32 * nq + u * 8 + lc;
        #pragma unroll
        for (int mh = 0; mh < 2; mh++)
            #pragma unroll
            for (int hh = 0; hh < 2; hh++) {
                const int row = 32 * rg + 16 * mh + 8 * hh + lr;
                float2* p = (float2*)(Zb + (size_t)row * Tz + col);
                float2 z = *p;
                z.x += acc[u][mh][2 * hh];
                z.y += acc[u][mh][2 * hh + 1];
                *p = z;
            }
    }
}

// ---------------------------------------------------------------------------
extern "C" void kernel_launch(void* const* d_in, const int* in_sizes, int n_in,
                              void* d_out, int out_size)
{
    const float* Q    = (const float*)d_in[0];   // (16, 1024, 128)
    const float* K    = (const float*)d_in[1];   // (16, 2047, 128)
    const float* bias = (const float*)d_in[2];   // (128, 1024)
    float* Z = (float*)d_out;                    // (16, 1024, 1024)

    static int configured = 0;
    if (!configured) {
        cudaFuncSetAttribute(band_kernel,
                             cudaFuncAttributeMaxDynamicSharedMemorySize, SMEM_BAND);
        cudaFuncSetAttribute(bias_kernel,
                             cudaFuncAttributeMaxDynamicSharedMemorySize, SMEM_BIAS);
        configured = 1;
    }

    conv_all_kernel<<<6270, 256>>>(Q, K, bias);

    dim3 bgrid(256, 4, 1);              // x = b*16 + w-strip, y = t-strip
    band_kernel<<<bgrid, 256, SMEM_BAND>>>(Z);

    dim3 pgrid(256, 8, 1);              // x = m-tile (64 rows), y = n-tile (128 cols)
    bias_kernel<<<pgrid, 256, SMEM_BIAS>>>(Z);
}

// round 14
// speedup vs baseline: 2.7345x; 1.3723x over previous
#include <cuda_runtime.h>
#include <cuda_fp16.h>
#include <stdint.h>

// SlidingWindowMatrixMult3D via mma.sync fp16 (single pass, fp32 accumulate).
// Z[b,w,t] = sum_c Q[b,w,c]*K[b,w+t,c] + sum_c Q[b,w,c]*bias[c,t]
// B=16, T=1024, C=128.
//
// R14: fused band+bias kernel. 64w x 256t strips (4 sub-tiles). Per sub-tile:
// band MMA over sliding 128-row K ring -> sheared scatter into smem ZS;
// bias tile staged into the ring's dead slots -> bias MMA; single write
// Z = ZS + bias. Eliminates the 128MB Z RMW of the two-kernel split.
// smem 69.6KB -> 3 CTA/SM.

#define Bz 16
#define Tz 1024
#define Cz 128
#define KTOT 2047
#define KPADROWS 128

// ---- global fp16 scratch ----
__device__ __half g_Qm[Bz * Tz * Cz];
__device__ __half g_Km[(Bz * KTOT + KPADROWS) * Cz];
__device__ __half g_Bm[Tz * Cz];     // transposed: [t][c]

// ---- shared layout: fp16 rows (256B) padded to 272B ----
#define RST 272u
#define OFF_Q 0u                 // 64 rows
#define OFF_K 17408u             // 128-slot ring (K band / bias tiles)
#define OFF_ZS 52224u            // 64 rows x 68 floats (272B) band staging
#define ZSS 68
#define SMEM_BYTES 69632u        // -> 3 CTA/SM

// ---------------------------------------------------------------------------
__device__ __forceinline__ uint32_t cvta_sh(const void* p) {
    uint32_t a;
    asm("{ .reg .u64 t; cvta.to.shared.u64 t, %1; cvt.u32.u64 %0, t; }"
        : "=r"(a) : "l"(p));
    return a;
}
__device__ __forceinline__ void cp16(uint32_t d, const void* s) {
    asm volatile("cp.async.ca.shared.global [%0], [%1], 16;" :: "r"(d), "l"(s));
}
#define CP_WAIT_ALL() asm volatile("cp.async.wait_all;" ::: "memory")

__device__ __forceinline__ void ldsm4(uint32_t* r, uint32_t a) {
    asm volatile("ldmatrix.sync.aligned.m8n8.x4.shared.b16 {%0,%1,%2,%3}, [%4];"
                 : "=r"(r[0]), "=r"(r[1]), "=r"(r[2]), "=r"(r[3]) : "r"(a));
}
__device__ __forceinline__ void ldsm2(uint32_t* r, uint32_t a) {
    asm volatile("ldmatrix.sync.aligned.m8n8.x2.shared.b16 {%0,%1}, [%2];"
                 : "=r"(r[0]), "=r"(r[1]) : "r"(a));
}
__device__ __forceinline__ void mma_f16(float* d, const uint32_t* a,
                                        uint32_t b0, uint32_t b1) {
    asm volatile(
        "mma.sync.aligned.m16n8k16.row.col.f32.f16.f16.f32 "
        "{%0,%1,%2,%3}, {%4,%5,%6,%7}, {%8,%9}, {%0,%1,%2,%3};"
        : "+f"(d[0]), "+f"(d[1]), "+f"(d[2]), "+f"(d[3])
        : "r"(a[0]), "r"(a[1]), "r"(a[2]), "r"(a[3]), "r"(b0), "r"(b1));
}

// ---------------------------------------------------------------------------
// pre-pass: Q, K (float4 path) + bias transpose -> fp16
__global__ void conv_all_kernel(const float* __restrict__ Q,
                                const float* __restrict__ K,
                                const float* __restrict__ bias)
{
    const int nQ = Bz * Tz * Cz / 4;        // 524288
    const int nK = Bz * KTOT * Cz / 4;      // 1048064
    const int nB = Tz * Cz / 4;             // 32768
    int i = blockIdx.x * blockDim.x + threadIdx.x;
    if (i < nQ + nK) {
        const float4* src;
        uint2* dst;
        int j;
        if (i < nQ) { src = (const float4*)Q; dst = (uint2*)g_Qm; j = i; }
        else        { src = (const float4*)K; dst = (uint2*)g_Km; j = i - nQ; }
        float4 v = __ldg(src + j);
        __half2 h01 = __floats2half2_rn(v.x, v.y);
        __half2 h23 = __floats2half2_rn(v.z, v.w);
        uint2 h;
        h.x = *(uint32_t*)&h01; h.y = *(uint32_t*)&h23;
        dst[j] = h;
    } else if (i < nQ + nK + nB) {
        int u = i - nQ - nK;
        int o = u * 4;
        int t = o >> 7, c = o & 127;
        float4 v;
        v.x = __ldg(bias + (c + 0) * Tz + t);
        v.y = __ldg(bias + (c + 1) * Tz + t);
        v.z = __ldg(bias + (c + 2) * Tz + t);
        v.w = __ldg(bias + (c + 3) * Tz + t);
        __half2 h01 = __floats2half2_rn(v.x, v.y);
        __half2 h23 = __floats2half2_rn(v.z, v.w);
        uint2 h;
        h.x = *(uint32_t*)&h01; h.y = *(uint32_t*)&h23;
        ((uint2*)g_Bm)[u] = h;
    }
}

// ---------------------------------------------------------------------------
// Fused kernel: 64w x 256t strip per CTA, 4 sub-tiles of 64x64.
__global__ void __launch_bounds__(256, 3)
swmm3d_fused(float* __restrict__ Z)
{
    extern __shared__ char sm[];
    const uint32_t sb = cvta_sh(sm);
    float* ZS = (float*)(sm + OFF_ZS);

    const int tid  = threadIdx.x;
    const int wid  = tid >> 5;
    const int lane = tid & 31;
    const int lr = lane >> 2;
    const int lc = (lane & 3) * 2;
    const int mt = wid >> 1;          // m16 block: rows 16mt..16mt+15
    const int s  = wid & 1;

    const int b  = blockIdx.x >> 4;
    const int w0 = (blockIdx.x & 15) * 64;
    const int t0 = blockIdx.y * 256;
    const int kbase = w0 + t0;

    const char* gq = (const char*)g_Qm + (size_t)(b * Tz + w0) * 256;
    const char* gk = (const char*)g_Km + (size_t)(b * KTOT + kbase) * 256;
    const char* gb = (const char*)g_Bm + (size_t)t0 * 256;

    // zero ring slot 127 (masked band reads on j=0 must see finite data)
    if (tid < 17)
        *(uint4*)(sm + OFF_K + 127u * RST + tid * 16) = make_uint4(0, 0, 0, 0);

    // prologue: Q (64 rows) + K ring rows 0..126
    for (int i = tid; i < 64 * 16; i += 256) {
        int r = i >> 4, c = i & 15;
        cp16(sb + OFF_Q + (uint32_t)r * RST + c * 16, gq + (size_t)r * 256 + c * 16);
    }
    for (int i = tid; i < 127 * 16; i += 256) {
        int r = i >> 4, c = i & 15;
        cp16(sb + OFF_K + (uint32_t)r * RST + c * 16, gk + (size_t)r * 256 + c * 16);
    }

    // ldmatrix lane components
    const uint32_t m8 = lane >> 3, mr = lane & 7;
    const uint32_t a_row = 16u * mt + ((m8 & 1) << 3) + mr;
    const uint32_t aA = sb + OFF_Q + a_row * RST + (m8 >> 1) * 16;
    const int rB  = (int)((m8 >> 1) * 8 + mr);
    const uint32_t cB = (m8 & 1) * 16;
    const uint32_t l16 = lane & 15;
    const int rB2 = (int)(l16 & 7);
    const uint32_t cB2 = (l16 >> 3) * 16;

    const int gnt0 = 2 * mt + 5 * s;   // band n-tile base for this warp

    #pragma unroll 1
    for (int j = 0; j < 4; j++) {
        const int wb = 64 * j;
        float* __restrict__ Zb = Z + ((size_t)b * Tz + w0) * Tz + t0 + wb;

        CP_WAIT_ALL();
        __syncthreads();                 // K window (and prior-iter stores) ready

        // ================= band MMA: 5 n-tiles =================
        float acc[5][4];
        #pragma unroll
        for (int u = 0; u < 5; u++)
            #pragma unroll
            for (int e = 0; e < 4; e++) acc[u][e] = 0.0f;

        const uint32_t bb0 = sb + OFF_K + (uint32_t)((wb + gnt0 * 8 + rB) & 127) * RST + cB;
        const uint32_t bb1 = sb + OFF_K + (uint32_t)((wb + (gnt0 + 2) * 8 + rB) & 127) * RST + cB;
        const uint32_t bb2 = sb + OFF_K + (uint32_t)((wb + (gnt0 + 4) * 8 + rB2) & 127) * RST + cB2;

        #pragma unroll
        for (int half = 0; half < 2; half++) {
            const uint32_t kb = (uint32_t)half * 128;
            uint32_t A[4][4];
            #pragma unroll
            for (int q = 0; q < 4; q++)
                ldsm4(A[q], aA + kb + q * 32);
            #pragma unroll
            for (int q = 0; q < 4; q++) {
                uint32_t b01[4], b23[4], b4[2];
                ldsm4(b01, bb0 + kb + q * 32);
                ldsm4(b23, bb1 + kb + q * 32);
                ldsm2(b4,  bb2 + kb + q * 32);
                mma_f16(acc[0], A[q], b01[0], b01[1]);
                mma_f16(acc[1], A[q], b01[2], b01[3]);
                mma_f16(acc[2], A[q], b23[0], b23[1]);
                mma_f16(acc[3], A[q], b23[2], b23[3]);
                mma_f16(acc[4], A[q], b4[0],  b4[1]);
            }
        }
        __syncthreads();                 // all ring reads complete

        // ---- stage bias tile j into dead ring slots [wb, wb+63] ----
        for (int i = tid; i < 64 * 16; i += 256) {
            int r = i >> 4, c = i & 15;
            cp16(sb + OFF_K + (uint32_t)((wb + r) & 127) * RST + c * 16,
                 gb + (size_t)(wb + r) * 256 + c * 16);
        }

        // ---- scatter band accs sheared into ZS (overlaps bias loads) ----
        #pragma unroll
        for (int u = 0; u < 5; u++) {
            const int n0 = (gnt0 + u) * 8 + lc;
            #pragma unroll
            for (int h = 0; h < 2; h++) {
                const int row = 16 * mt + lr + 8 * h;
                const int j0 = n0 - row;
                if ((unsigned)j0 < 64u)       ZS[row * ZSS + j0]     = acc[u][2 * h];
                if ((unsigned)(j0 + 1) < 64u) ZS[row * ZSS + j0 + 1] = acc[u][2 * h + 1];
            }
        }

        CP_WAIT_ALL();
        __syncthreads();                 // bias tile + ZS visible

        // ================= bias MMA: warp covers rows 16mt.., cols 32s.. ====
        float bacc[4][4];
        #pragma unroll
        for (int u = 0; u < 4; u++)
            #pragma unroll
            for (int e = 0; e < 4; e++) bacc[u][e] = 0.0f;

        const uint32_t pb0 = sb + OFF_K + (uint32_t)((wb + 32 * s + rB) & 127) * RST + cB;
        const uint32_t pb1 = sb + OFF_K + (uint32_t)((wb + 32 * s + 16 + rB) & 127) * RST + cB;

        #pragma unroll
        for (int kt = 0; kt < 8; kt++) {
            uint32_t A[4];
            ldsm4(A, aA + kt * 32);
            uint32_t bh[4];
            ldsm4(bh, pb0 + kt * 32);
            mma_f16(bacc[0], A, bh[0], bh[1]);
            mma_f16(bacc[1], A, bh[2], bh[3]);
            ldsm4(bh, pb1 + kt * 32);
            mma_f16(bacc[2], A, bh[0], bh[1]);
            mma_f16(bacc[3], A, bh[2], bh[3]);
        }
        __syncthreads();                 // bias slot reads done (ZS reads below are ok:
                                         // next scatter happens after next band sync)

        // ---- prefetch next 64 K rows (hidden behind the Z epilogue) ----
        if (j < 3) {
            for (int i = tid; i < 64 * 16; i += 256) {
                int r = i >> 4, c = i & 15;
                int rel = wb + 127 + r;
                cp16(sb + OFF_K + (uint32_t)(rel & 127) * RST + c * 16,
                     gk + (size_t)rel * 256 + c * 16);
            }
        }

        // ---- epilogue: Z = ZS (band) + bacc (bias), single write ----
        #pragma unroll
        for (int u = 0; u < 4; u++) {
            const int col = 32 * s + u * 8 + lc;
            #pragma unroll
            for (int h = 0; h < 2; h++) {
                const int row = 16 * mt + lr + 8 * h;
                float2 zv = *(float2*)&ZS[row * ZSS + col];
                float2 o;
                o.x = zv.x + bacc[u][2 * h];
                o.y = zv.y + bacc[u][2 * h + 1];
                *(float2*)(Zb + (size_t)row * Tz + col) = o;
            }
        }
    }
}

// ---------------------------------------------------------------------------
extern "C" void kernel_launch(void* const* d_in, const int* in_sizes, int n_in,
                              void* d_out, int out_size)
{
    const float* Q    = (const float*)d_in[0];   // (16, 1024, 128)
    const float* K    = (const float*)d_in[1];   // (16, 2047, 128)
    const float* bias = (const float*)d_in[2];   // (128, 1024)
    float* Z = (float*)d_out;                    // (16, 1024, 1024)

    static int configured = 0;
    if (!configured) {
        cudaFuncSetAttribute(swmm3d_fused,
                             cudaFuncAttributeMaxDynamicSharedMemorySize, SMEM_BYTES);
        configured = 1;
    }

    conv_all_kernel<<<6270, 256>>>(Q, K, bias);

    dim3 grid(256, 4, 1);   // x = b*16 + w-strip, y = t-strip
    swmm3d_fused<<<grid, 256, SMEM_BYTES>>>(Z);
}